// round 12
// baseline (speedup 1.0000x reference)
#include <cuda_runtime.h>
#include <cuda_bf16.h>
#include <cuda_fp16.h>
#include <cstdint>

#define BB 1024
#define AA 200
#define DD 128
#define INV_SQRT_D 0.08838834764831845f
#define LOG2E 1.4426950408889634f

// ---------------- persistent scratch: packed weight fragments only -------------
__device__ uint2 g_FWs[16*8*32];     // W_step^ fragments (pre-scaled by 0.25*log2e)
__device__ uint2 g_FWn[32*8*32];     // W_node cols 0..255 (K,V) fragments
__device__ uint2 g_FWc[16*8*32];     // Wc = Wn[:,256:384] @ Wo^T fragments

// ---------------- helpers ------------------------------------------------------
__device__ __forceinline__ uint16_t f2b(float x){
    return __bfloat16_as_ushort(__float2bfloat16(x));
}
__device__ __forceinline__ uint32_t pk2(float a, float b){
    return (uint32_t)f2b(a) | ((uint32_t)f2b(b) << 16);
}
__device__ __forceinline__ uint32_t f2h2(float lo, float hi){
    uint32_t r;
    asm("cvt.rn.f16x2.f32 %0, %1, %2;" : "=r"(r) : "f"(hi), "f"(lo));
    return r;
}
__device__ __forceinline__ uint32_t hex2(uint32_t x){
    uint32_t r;
    asm("ex2.approx.f16x2 %0, %1;" : "=r"(r) : "r"(x));
    return r;
}
__device__ __forceinline__ uint32_t hadd2u(uint32_t a, uint32_t b){
    __half2 x = *reinterpret_cast<__half2*>(&a);
    __half2 y = *reinterpret_cast<__half2*>(&b);
    __half2 r = __hadd2(x, y);
    return *reinterpret_cast<uint32_t*>(&r);
}
__device__ __forceinline__ float2 h2f2(uint32_t u){
    __half2 h = *reinterpret_cast<__half2*>(&u);
    return __half22float2(h);
}
__device__ __forceinline__ float wredsum(float v){
    #pragma unroll
    for (int o = 16; o; o >>= 1) v += __shfl_xor_sync(0xffffffffu, v, o);
    return v;
}
__device__ __forceinline__ float qredsum(float v){
    v += __shfl_xor_sync(0xffffffffu, v, 1);
    v += __shfl_xor_sync(0xffffffffu, v, 2);
    return v;
}
__device__ __forceinline__ void mma16816(float* d, const uint32_t* a, const uint32_t* b){
    asm volatile(
      "mma.sync.aligned.m16n8k16.row.col.f32.bf16.bf16.f32 "
      "{%0,%1,%2,%3}, {%4,%5,%6,%7}, {%8,%9}, {%0,%1,%2,%3};\n"
      : "+f"(d[0]), "+f"(d[1]), "+f"(d[2]), "+f"(d[3])
      : "r"(a[0]), "r"(a[1]), "r"(a[2]), "r"(a[3]), "r"(b[0]), "r"(b[1]));
}
__device__ __forceinline__ void mma16816h(float* d, const uint32_t* a, const uint32_t* b){
    asm volatile(
      "mma.sync.aligned.m16n8k16.row.col.f32.f16.f16.f32 "
      "{%0,%1,%2,%3}, {%4,%5,%6,%7}, {%8,%9}, {%0,%1,%2,%3};\n"
      : "+f"(d[0]), "+f"(d[1]), "+f"(d[2]), "+f"(d[3])
      : "r"(a[0]), "r"(a[1]), "r"(a[2]), "r"(a[3]), "r"(b[0]), "r"(b[1]));
}
__device__ __forceinline__ void ldmat_x2_trans(uint32_t& r0, uint32_t& r1, uint32_t addr){
    asm volatile("ldmatrix.sync.aligned.m8n8.x2.trans.shared.b16 {%0,%1}, [%2];"
        : "=r"(r0), "=r"(r1) : "r"(addr));
}
__device__ __forceinline__ void mma_chain(float* acc, const uint32_t a[8][4],
                                          const uint2* __restrict__ F, int nt, int lane){
    #pragma unroll
    for (int kk = 0; kk < 8; kk++){
        uint2 u = __ldg(&F[(nt*8 + kk)*32 + lane]);
        uint32_t bb[2] = {u.x, u.y};
        mma16816(acc, a[kk], bb);
    }
}

// ---------------- prep: pack all B-fragments (Wc dot computed inline) ----------
__global__ void k_prep(const float* __restrict__ Ws, const float* __restrict__ Wn,
                       const float* __restrict__ Wo){
    int t = blockIdx.x*256 + threadIdx.x;
    int which, id;
    if (t < 4096)       { which = 0; id = t; }
    else if (t < 12288) { which = 1; id = t - 4096; }
    else                { which = 2; id = t - 12288; }
    int lane = id & 31, kk = (id >> 5) & 7, nt = id >> 8;
    int qq = lane & 3, gg = lane >> 2;
    int k0 = kk*16 + qq*2, n = nt*8 + gg;
    float v0, v1, v2, v3;
    if (which == 0){
        float s = 0.25f * LOG2E;
        v0 = Ws[(k0  )*128 + n]*s; v1 = Ws[(k0+1)*128 + n]*s;
        v2 = Ws[(k0+8)*128 + n]*s; v3 = Ws[(k0+9)*128 + n]*s;
    } else if (which == 1){
        v0 = Wn[(k0  )*384 + n]; v1 = Wn[(k0+1)*384 + n];
        v2 = Wn[(k0+8)*384 + n]; v3 = Wn[(k0+9)*384 + n];
    } else {
        const float* wo = Wo + n*128;
        const float* wa = Wn + (k0  )*384 + 256;
        const float* wb = Wn + (k0+1)*384 + 256;
        const float* wc = Wn + (k0+8)*384 + 256;
        const float* wd = Wn + (k0+9)*384 + 256;
        v0 = v1 = v2 = v3 = 0.f;
        #pragma unroll 4
        for (int d = 0; d < 128; d++){
            float o = wo[d];
            v0 = fmaf(wa[d], o, v0); v1 = fmaf(wb[d], o, v1);
            v2 = fmaf(wc[d], o, v2); v3 = fmaf(wd[d], o, v3);
        }
    }
    uint2 u; u.x = pk2(v0, v1); u.y = pk2(v2, v3);
    if (which == 0)      g_FWs[id] = u;
    else if (which == 1) g_FWn[id] = u;
    else                 g_FWc[id] = u;
}

// ---------------- fused kernel (832 threads = 26 warps = 13 tiles x 2 halves) --
#define F_K   0
#define F_L   56576
#define F_V   113152
#define F_LA  169728
#define F_MP  222976
#define F_FC  225024
#define F_PH  225536
#define F_POS 225792
#define F_ACT 226304
#define F_ES  227136
#define F_LP  230464
#define FUSED_SMEM 230528

__global__ void __launch_bounds__(832,1) k_fused(
    const float* __restrict__ agent, const int* __restrict__ act_g,
    const float* __restrict__ Wp, const float* __restrict__ Wf,
    float* __restrict__ out, int mode)
{
    extern __shared__ char sm[];
    uint16_t* sK  = (uint16_t*)(sm + F_K);     // X -> K in place
    uint16_t* sL  = (uint16_t*)(sm + F_L);     // L2 (bf16)
    uint16_t* sV  = (uint16_t*)(sm + F_V);     // V (fp16)
    uint4*    sLA = (uint4*)(sm + F_LA);
    float*    sMP = (float*)(sm + F_MP);
    float*    sFC = (float*)(sm + F_FC);
    uint16_t* sPH = (uint16_t*)(sm + F_PH);
    int16_t*  sPos= (int16_t*)(sm + F_POS);
    int*      sAct= (int*)(sm + F_ACT);
    float*    sES = (float*)(sm + F_ES);
    float*    sLP = (float*)(sm + F_LP);

    int b = blockIdx.x, tid = threadIdx.x;
    int lane = tid & 31, w = tid >> 5, qq = lane & 3, gg = lane >> 2;
    int t = w >> 1, half = w & 1;
    int r1 = t*16 + gg, r2 = r1 + 8;

    // ---- load X (fp32 -> bf16) + small tables ----
    {
        const float2* Xg = (const float2*)(agent + (size_t)b*AA*DD);
        uint32_t* dX = (uint32_t*)sK;
        for (int i = tid; i < AA*64; i += 832){
            int r = i >> 6, c = i & 63;
            float2 v = Xg[i];
            dX[r*68 + c] = pk2(v.x, v.y);
        }
        for (int i = 200*68 + tid; i < 208*68; i += 832) dX[i] = 0;
        if (tid < 128) sPH[tid] = f2b(Wp[tid]);
        if (tid < 256) sPos[tid] = -1;
        if (tid < 208) sAct[tid] = (tid < AA) ? act_g[b*AA + tid] : 0;
    }
    __syncthreads();
    if (tid < AA) sPos[sAct[tid]] = (int16_t)tid;
    // ---- FC stage A: column sums from bf16 X in smem ----
    if (tid < 512){
        int part = tid >> 7, j = tid & 127;
        const uint16_t* xp = sK + part*50*136 + j;
        float s = 0.f;
        #pragma unroll 5
        for (int r = 0; r < 50; r++)
            s += __uint_as_float(((uint32_t)xp[r*136]) << 16);
        sMP[tid] = s;
    }
    __syncthreads();
    if (tid < 128)
        sFC[tid] = (sMP[tid] + sMP[128+tid] + sMP[256+tid] + sMP[384+tid]) * (1.0f/AA);
    __syncthreads();
    float accB = 0.f;
    if (tid < 512){
        int q4 = tid >> 7, j = tid & 127;
        #pragma unroll 8
        for (int d = q4*32; d < q4*32 + 32; d++) accB = fmaf(sFC[d], Wf[d*128 + j], accB);
    }
    __syncthreads();
    if (tid < 512) sMP[tid] = accB;
    __syncthreads();
    if (tid < 128)
        sFC[tid] = (0.25f*LOG2E)*(sMP[tid] + sMP[128+tid] + sMP[256+tid] + sMP[384+tid]);
    __syncthreads();

    // ---- Phase Q: gather(X) @ Ws + FC -> registers (exact A-frag layout) ----
    uint32_t qa[4][4];
    {
        uint32_t ag[8][4];
        const uint16_t* p1 = (r1 == 0) ? sPH : sK + sAct[r1-1]*136;
        const uint16_t* p2 = sK + sAct[r2-1]*136;
        #pragma unroll
        for (int kk = 0; kk < 8; kk++){
            ag[kk][0] = *(const uint32_t*)(p1 + kk*16 + qq*2);
            ag[kk][1] = *(const uint32_t*)(p2 + kk*16 + qq*2);
            ag[kk][2] = *(const uint32_t*)(p1 + kk*16 + qq*2 + 8);
            ag[kk][3] = *(const uint32_t*)(p2 + kk*16 + qq*2 + 8);
        }
        #pragma unroll
        for (int ln = 0; ln < 8; ln++){
            float acc[4] = {0.f,0.f,0.f,0.f};
            mma_chain(acc, ag, g_FWs, half*8 + ln, lane);
            int d0 = (half*8 + ln)*8 + qq*2;
            float2 fc = *(const float2*)(sFC + d0);
            int hh = ln >> 1, odd = ln & 1;
            qa[hh][odd*2]   = pk2(fc.x + acc[0], fc.y + acc[1]);   // row r1
            qa[hh][odd*2+1] = pk2(fc.x + acc[2], fc.y + acc[3]);   // row r2
        }
    }
    // ---- own-row X fragments, then L2 phase ----
    uint32_t ax[8][4];
    {
        const uint16_t* p1 = sK + r1*136;
        const uint16_t* p2 = sK + r2*136;
        #pragma unroll
        for (int kk = 0; kk < 8; kk++){
            ax[kk][0] = *(const uint32_t*)(p1 + kk*16 + qq*2);
            ax[kk][1] = *(const uint32_t*)(p2 + kk*16 + qq*2);
            ax[kk][2] = *(const uint32_t*)(p1 + kk*16 + qq*2 + 8);
            ax[kk][3] = *(const uint32_t*)(p2 + kk*16 + qq*2 + 8);
        }
        #pragma unroll 2
        for (int ln = 0; ln < 8; ln++){
            float acc[4] = {0.f,0.f,0.f,0.f};
            mma_chain(acc, ax, g_FWc, half*8 + ln, lane);
            int d0 = (half*8 + ln)*8 + qq*2;
            *(uint32_t*)(sL + r1*136 + d0) = pk2(acc[0], acc[1]);
            *(uint32_t*)(sL + r2*136 + d0) = pk2(acc[2], acc[3]);
        }
    }
    __syncthreads();   // all X reads (ag, ax) complete before in-place K writes

    // ---- Phase K (overwrite X) + V (fp16) ----
    {
        #pragma unroll 2
        for (int ln = 0; ln < 8; ln++){
            float acc[4] = {0.f,0.f,0.f,0.f};
            mma_chain(acc, ax, g_FWn, half*8 + ln, lane);
            int d0 = (half*8 + ln)*8 + qq*2;
            *(uint32_t*)(sK + r1*136 + d0) = pk2(acc[0], acc[1]);
            *(uint32_t*)(sK + r2*136 + d0) = pk2(acc[2], acc[3]);
        }
        #pragma unroll 2
        for (int ln = 0; ln < 8; ln++){
            float acc[4] = {0.f,0.f,0.f,0.f};
            mma_chain(acc, ax, g_FWn, 16 + half*8 + ln, lane);
            int d0 = (half*8 + ln)*8 + qq*2;
            *(uint32_t*)(sV + r1*136 + d0) = f2h2(acc[0], acc[1]);
            *(uint32_t*)(sV + r2*136 + d0) = f2h2(acc[2], acc[3]);
        }
    }
    __syncthreads();

    // ---- decode: masks ----
    int act1 = sAct[r1], act2 = sAct[r2];
    unsigned long long dead1 = 0, dead2 = 0, sel1 = 0, sel2 = 0;
    #pragma unroll
    for (int nt = 0; nt < 26; nt++){
        #pragma unroll
        for (int e = 0; e < 2; e++){
            int c = nt*8 + qq*2 + e;
            int p = (int)sPos[c];
            unsigned long long bit = 1ull << (nt*2 + e);
            if (p < r1)    dead1 |= bit;
            if (p < r2)    dead2 |= bit;
            if (c == act1) sel1  |= bit;
            if (c == act2) sel2  |= bit;
        }
    }

    // ---- attention: 4 heads per warp, streaming f16x2-exp softmax ----
    uint32_t sVu = (uint32_t)__cvta_generic_to_shared(sV) + (uint32_t)((lane & 15)*272);
    uint32_t la[4][4];
    #pragma unroll
    for (int hh = 0; hh < 4; hh++){
        int h = half*4 + hh;
        uint32_t sum1h = 0, sum2h = 0;
        float h0[4] = {0,0,0,0}, h1[4] = {0,0,0,0};
        #pragma unroll 1
        for (int kt = 0; kt < 13; kt++){
            float s0[4] = {0,0,0,0}, s1[4] = {0,0,0,0};
            const uint16_t* kb  = sK + (kt*16 + gg)*136 + h*16 + qq*2;
            const uint16_t* kb2 = kb + 8*136;
            uint32_t b0[2] = { *(const uint32_t*)kb,  *(const uint32_t*)(kb+8)  };
            uint32_t b1[2] = { *(const uint32_t*)kb2, *(const uint32_t*)(kb2+8) };
            mma16816(s0, qa[hh], b0);
            mma16816(s1, qa[hh], b1);
            int sh = kt*4;
            s0[0] = ((dead1>>(sh  ))&1) ? -100.f : s0[0];
            s0[1] = ((dead1>>(sh+1))&1) ? -100.f : s0[1];
            s1[0] = ((dead1>>(sh+2))&1) ? -100.f : s1[0];
            s1[1] = ((dead1>>(sh+3))&1) ? -100.f : s1[1];
            s0[2] = ((dead2>>(sh  ))&1) ? -100.f : s0[2];
            s0[3] = ((dead2>>(sh+1))&1) ? -100.f : s0[3];
            s1[2] = ((dead2>>(sh+2))&1) ? -100.f : s1[2];
            s1[3] = ((dead2>>(sh+3))&1) ? -100.f : s1[3];
            uint32_t pa[4];
            pa[0] = hex2(f2h2(s0[0], s0[1]));   // row r1
            pa[1] = hex2(f2h2(s0[2], s0[3]));   // row r2
            pa[2] = hex2(f2h2(s1[0], s1[1]));
            pa[3] = hex2(f2h2(s1[2], s1[3]));
            sum1h = hadd2u(sum1h, pa[0]); sum1h = hadd2u(sum1h, pa[2]);
            sum2h = hadd2u(sum2h, pa[1]); sum2h = hadd2u(sum2h, pa[3]);
            uint32_t v0, v1;
            uint32_t ad = sVu + (uint32_t)((kt*16*136 + h*16)*2);
            ldmat_x2_trans(v0, v1, ad);
            { uint32_t bv[2] = {v0, v1}; mma16816h(h0, pa, bv); }
            ldmat_x2_trans(v0, v1, ad + 16);
            { uint32_t bv[2] = {v0, v1}; mma16816h(h1, pa, bv); }
        }
        float2 f1 = h2f2(sum1h), f2v = h2f2(sum2h);
        float sum1 = qredsum(f1.x + f1.y);
        float sum2 = qredsum(f2v.x + f2v.y);
        float inv1 = 1.0f / sum1;
        float inv2 = (sum2 > 0.f) ? 1.0f / sum2 : 0.f;
        la[hh][0] = pk2(h0[0]*inv1, h0[1]*inv1);
        la[hh][1] = pk2(h0[2]*inv2, h0[3]*inv2);
        la[hh][2] = pk2(h1[0]*inv1, h1[1]*inv1);
        la[hh][3] = pk2(h1[2]*inv2, h1[3]*inv2);
    }

    // ---- exchange glimpse fragments between tile halves ----
    #pragma unroll
    for (int hh = 0; hh < 4; hh++)
        sLA[(w*4 + hh)*32 + lane] = make_uint4(la[hh][0], la[hh][1], la[hh][2], la[hh][3]);
    __syncthreads();
    uint32_t pl[4][4];
    {
        int pw = w ^ 1;
        #pragma unroll
        for (int hh = 0; hh < 4; hh++){
            uint4 u = sLA[(pw*4 + hh)*32 + lane];
            pl[hh][0] = u.x; pl[hh][1] = u.y; pl[hh][2] = u.z; pl[hh][3] = u.w;
        }
    }

    // ---- logits over this warp's 13-nt half, all 8 heads ----
    float es1 = 0.f, es2 = 0.f, sv1 = 0.f, sv2 = 0.f;
    int ntb = half*13;
    #pragma unroll 1
    for (int j = 0; j < 13; j++){
        int nt = ntb + j;
        float acc[4] = {0,0,0,0};
        const uint16_t* lb = sL + (nt*8 + gg)*136 + qq*2;
        #pragma unroll
        for (int h = 0; h < 8; h++){
            const uint32_t* A = ((h >> 2) == half) ? la[h & 3] : pl[h & 3];
            uint32_t bb[2] = { *(const uint32_t*)(lb + h*16),
                               *(const uint32_t*)(lb + h*16 + 8) };
            mma16816(acc, A, bb);
        }
        int sh = nt*2;
        #pragma unroll
        for (int e = 0; e < 2; e++){
            float t1 = 10.f - 20.f/(__expf(2.f*INV_SQRT_D*acc[e])   + 1.f);
            float t2 = 10.f - 20.f/(__expf(2.f*INV_SQRT_D*acc[2+e]) + 1.f);
            if (!((dead1>>(sh+e))&1)) es1 += __expf(t1 - 10.f);
            if (!((dead2>>(sh+e))&1)) es2 += __expf(t2 - 10.f);
            if ((sel1>>(sh+e))&1) sv1 = t1;
            if ((sel2>>(sh+e))&1) sv2 = t2;
        }
    }
    es1 = qredsum(es1); es2 = qredsum(es2);
    sv1 = qredsum(sv1); sv2 = qredsum(sv2);
    if (qq == 0){
        float* e = sES + (w*8 + gg)*4;
        e[0] = es1; e[1] = es2; e[2] = sv1; e[3] = sv2;
    }
    __syncthreads();
    float lpw = 0.f;
    if (half == 0 && qq == 0){
        const float* e0 = sES + (w*8 + gg)*4;
        const float* e1 = sES + ((w+1)*8 + gg)*4;
        float tes1 = e0[0]+e1[0], tes2 = e0[1]+e1[1];
        float tsv1 = e0[2]+e1[2], tsv2 = e0[3]+e1[3];
        lpw = tsv1 - 10.f - __logf(tes1);
        if (r2 < AA) lpw += tsv2 - 10.f - __logf(tes2);
    }
    lpw = wredsum(lpw);
    if (half == 0 && lane == 0) sLP[t] = lpw;
    __syncthreads();
    float* lp_out = mode ? (out + BB*AA) : out;
    if (tid == 0){
        float s = 0.f;
        #pragma unroll
        for (int k = 0; k < 13; k++) s += sLP[k];
        lp_out[b] = s;
    }
    if (mode){
        for (int i = tid; i < AA; i += 832) out[b*AA + i] = (float)sAct[i];
    }
}

// ---------------- launch -------------------------------------------------------
extern "C" void kernel_launch(void* const* d_in, const int* in_sizes, int n_in,
                              void* d_out, int out_size){
    const float* agent = (const float*)d_in[0];
    const int*   act   = (const int*)d_in[1];
    const float* Wp    = (const float*)d_in[2];
    const float* Wn    = (const float*)d_in[3];
    const float* Wf    = (const float*)d_in[4];
    const float* Ws    = (const float*)d_in[5];
    const float* Wo    = (const float*)d_in[6];
    float* out = (float*)d_out;

    cudaFuncSetAttribute(k_fused, cudaFuncAttributeMaxDynamicSharedMemorySize, FUSED_SMEM);

    k_prep<<<64, 256>>>(Ws, Wn, Wo);

    int mode = (out_size >= BB*AA) ? 1 : 0;
    k_fused<<<BB, 832, FUSED_SMEM>>>(agent, act, Wp, Wf, out, mode);
}

// round 13
// speedup vs baseline: 1.9051x; 1.9051x over previous
#include <cuda_runtime.h>
#include <cuda_bf16.h>
#include <cuda_fp16.h>
#include <cstdint>

#define BB 1024
#define AA 200
#define DD 128
#define INV_SQRT_D 0.08838834764831845f
#define LOG2E 1.4426950408889634f

// ---------------- persistent scratch: packed weight fragments only -------------
__device__ uint2 g_FWs[16*8*32];     // W_step fragments (pre-scaled by 0.25*log2e)
__device__ uint2 g_FWn[32*8*32];     // W_node cols 0..255 (K,V) fragments
__device__ uint2 g_FWc[16*8*32];     // Wc = Wn[:,256:384] @ Wo^T fragments

// ---------------- helpers ------------------------------------------------------
__device__ __forceinline__ uint16_t f2b(float x){
    return __bfloat16_as_ushort(__float2bfloat16(x));
}
__device__ __forceinline__ uint32_t pk2(float a, float b){
    return (uint32_t)f2b(a) | ((uint32_t)f2b(b) << 16);
}
__device__ __forceinline__ uint32_t f2h2(float lo, float hi){
    uint32_t r;
    asm("cvt.rn.f16x2.f32 %0, %1, %2;" : "=r"(r) : "f"(hi), "f"(lo));
    return r;
}
__device__ __forceinline__ uint32_t hex2(uint32_t x){
    uint32_t r;
    asm("ex2.approx.f16x2 %0, %1;" : "=r"(r) : "r"(x));
    return r;
}
__device__ __forceinline__ uint32_t hadd2u(uint32_t a, uint32_t b){
    __half2 x = *reinterpret_cast<__half2*>(&a);
    __half2 y = *reinterpret_cast<__half2*>(&b);
    __half2 r = __hadd2(x, y);
    return *reinterpret_cast<uint32_t*>(&r);
}
__device__ __forceinline__ float2 h2f2(uint32_t u){
    __half2 h = *reinterpret_cast<__half2*>(&u);
    return __half22float2(h);
}
__device__ __forceinline__ float fex2(float x){
    float r; asm("ex2.approx.ftz.f32 %0, %1;" : "=f"(r) : "f"(x)); return r;
}
__device__ __forceinline__ float frcpa(float x){
    float r; asm("rcp.approx.ftz.f32 %0, %1;" : "=f"(r) : "f"(x)); return r;
}
__device__ __forceinline__ float flg2(float x){
    float r; asm("lg2.approx.ftz.f32 %0, %1;" : "=f"(r) : "f"(x)); return r;
}
__device__ __forceinline__ float wredsum(float v){
    #pragma unroll
    for (int o = 16; o; o >>= 1) v += __shfl_xor_sync(0xffffffffu, v, o);
    return v;
}
__device__ __forceinline__ float qredsum(float v){
    v += __shfl_xor_sync(0xffffffffu, v, 1);
    v += __shfl_xor_sync(0xffffffffu, v, 2);
    return v;
}
__device__ __forceinline__ void mma16816(float* d, const uint32_t* a, const uint32_t* b){
    asm volatile(
      "mma.sync.aligned.m16n8k16.row.col.f32.bf16.bf16.f32 "
      "{%0,%1,%2,%3}, {%4,%5,%6,%7}, {%8,%9}, {%0,%1,%2,%3};\n"
      : "+f"(d[0]), "+f"(d[1]), "+f"(d[2]), "+f"(d[3])
      : "r"(a[0]), "r"(a[1]), "r"(a[2]), "r"(a[3]), "r"(b[0]), "r"(b[1]));
}
__device__ __forceinline__ void mma16816h(float* d, const uint32_t* a, const uint32_t* b){
    asm volatile(
      "mma.sync.aligned.m16n8k16.row.col.f32.f16.f16.f32 "
      "{%0,%1,%2,%3}, {%4,%5,%6,%7}, {%8,%9}, {%0,%1,%2,%3};\n"
      : "+f"(d[0]), "+f"(d[1]), "+f"(d[2]), "+f"(d[3])
      : "r"(a[0]), "r"(a[1]), "r"(a[2]), "r"(a[3]), "r"(b[0]), "r"(b[1]));
}
__device__ __forceinline__ void ldmat_x4(uint32_t& r0, uint32_t& r1, uint32_t& r2,
                                         uint32_t& r3, uint32_t addr){
    asm volatile("ldmatrix.sync.aligned.m8n8.x4.shared.b16 {%0,%1,%2,%3}, [%4];"
        : "=r"(r0), "=r"(r1), "=r"(r2), "=r"(r3) : "r"(addr));
}
__device__ __forceinline__ void ldmat_x2(uint32_t& r0, uint32_t& r1, uint32_t addr){
    asm volatile("ldmatrix.sync.aligned.m8n8.x2.shared.b16 {%0,%1}, [%2];"
        : "=r"(r0), "=r"(r1) : "r"(addr));
}
__device__ __forceinline__ void ldmat_x2_trans(uint32_t& r0, uint32_t& r1, uint32_t addr){
    asm volatile("ldmatrix.sync.aligned.m8n8.x2.trans.shared.b16 {%0,%1}, [%2];"
        : "=r"(r0), "=r"(r1) : "r"(addr));
}
__device__ __forceinline__ void mma_chain(float* acc, const uint32_t a[8][4],
                                          const uint2* __restrict__ F, int nt, int lane){
    #pragma unroll
    for (int kk = 0; kk < 8; kk++){
        uint2 u = __ldg(&F[(nt*8 + kk)*32 + lane]);
        uint32_t bb[2] = {u.x, u.y};
        mma16816(acc, a[kk], bb);
    }
}

// ---------------- prep: pack all B-fragments (Wc dot computed inline) ----------
__global__ void k_prep(const float* __restrict__ Ws, const float* __restrict__ Wn,
                       const float* __restrict__ Wo){
    int t = blockIdx.x*256 + threadIdx.x;
    int which, id;
    if (t < 4096)       { which = 0; id = t; }
    else if (t < 12288) { which = 1; id = t - 4096; }
    else                { which = 2; id = t - 12288; }
    int lane = id & 31, kk = (id >> 5) & 7, nt = id >> 8;
    int qq = lane & 3, gg = lane >> 2;
    int k0 = kk*16 + qq*2, n = nt*8 + gg;
    float v0, v1, v2, v3;
    if (which == 0){
        float s = 0.25f * LOG2E;
        v0 = Ws[(k0  )*128 + n]*s; v1 = Ws[(k0+1)*128 + n]*s;
        v2 = Ws[(k0+8)*128 + n]*s; v3 = Ws[(k0+9)*128 + n]*s;
    } else if (which == 1){
        v0 = Wn[(k0  )*384 + n]; v1 = Wn[(k0+1)*384 + n];
        v2 = Wn[(k0+8)*384 + n]; v3 = Wn[(k0+9)*384 + n];
    } else {
        const float* wo = Wo + n*128;
        const float* wa = Wn + (k0  )*384 + 256;
        const float* wb = Wn + (k0+1)*384 + 256;
        const float* wc = Wn + (k0+8)*384 + 256;
        const float* wd = Wn + (k0+9)*384 + 256;
        v0 = v1 = v2 = v3 = 0.f;
        #pragma unroll 4
        for (int d = 0; d < 128; d++){
            float o = wo[d];
            v0 = fmaf(wa[d], o, v0); v1 = fmaf(wb[d], o, v1);
            v2 = fmaf(wc[d], o, v2); v3 = fmaf(wd[d], o, v3);
        }
    }
    uint2 u; u.x = pk2(v0, v1); u.y = pk2(v2, v3);
    if (which == 0)      g_FWs[id] = u;
    else if (which == 1) g_FWn[id] = u;
    else                 g_FWc[id] = u;
}

// ---------------- fused kernel (512 threads; 13 working warps) -----------------
#define F_K   0
#define F_L   56576
#define F_V   113152
#define F_MP  169728
#define F_FC  171776
#define F_PH  172288
#define F_POS 172800
#define F_ACT 173312
#define F_LP  174208
#define FUSED_SMEM 174272

__global__ void __launch_bounds__(512) k_fused(
    const float* __restrict__ agent, const int* __restrict__ act_g,
    const float* __restrict__ Wp, const float* __restrict__ Wf,
    float* __restrict__ out, int mode)
{
    extern __shared__ char sm[];
    uint16_t* sK  = (uint16_t*)(sm + F_K);     // X -> K in place
    uint16_t* sL  = (uint16_t*)(sm + F_L);     // L2 (bf16)
    uint16_t* sV  = (uint16_t*)(sm + F_V);     // V (fp16)
    float*    sMP = (float*)(sm + F_MP);
    float*    sFC = (float*)(sm + F_FC);
    uint16_t* sPH = (uint16_t*)(sm + F_PH);
    int16_t*  sPos= (int16_t*)(sm + F_POS);
    int*      sAct= (int*)(sm + F_ACT);
    float*    sLP = (float*)(sm + F_LP);

    int b = blockIdx.x, tid = threadIdx.x;
    int lane = tid & 31, w = tid >> 5, qq = lane & 3, gg = lane >> 2;
    int r1 = w*16 + gg, r2 = r1 + 8;

    // ---- load X (fp32 -> bf16) + tables ----
    {
        const float2* Xg = (const float2*)(agent + (size_t)b*AA*DD);
        uint32_t* dX = (uint32_t*)sK;
        for (int i = tid; i < AA*64; i += 512){
            int r = i >> 6, c = i & 63;
            float2 v = Xg[i];
            dX[r*68 + c] = pk2(v.x, v.y);
        }
        for (int i = 200*68 + tid; i < 208*68; i += 512) dX[i] = 0;
        if (tid < 128) sPH[tid] = f2b(Wp[tid]);
        if (tid < 256) sPos[tid] = -1;
        if (tid < 208) sAct[tid] = (tid < AA) ? act_g[b*AA + tid] : 0;
    }
    __syncthreads();
    if (tid < AA) sPos[sAct[tid]] = (int16_t)tid;
    // ---- FC stage A: column sums from bf16 X in smem ----
    {
        int part = tid >> 7, j = tid & 127;
        const uint16_t* xp = sK + part*50*136 + j;
        float s = 0.f;
        #pragma unroll 5
        for (int r = 0; r < 50; r++)
            s += __uint_as_float(((uint32_t)xp[r*136]) << 16);
        sMP[tid] = s;
    }
    __syncthreads();
    if (tid < 128)
        sFC[tid] = (sMP[tid] + sMP[128+tid] + sMP[256+tid] + sMP[384+tid]) * (1.0f/AA);
    __syncthreads();
    {
        int q4 = tid >> 7, j = tid & 127;
        float accB = 0.f;
        #pragma unroll 8
        for (int d = q4*32; d < q4*32 + 32; d++) accB = fmaf(sFC[d], Wf[d*128 + j], accB);
        __syncthreads();
        sMP[tid] = accB;
    }
    __syncthreads();
    if (tid < 128)
        sFC[tid] = (0.25f*LOG2E)*(sMP[tid] + sMP[128+tid] + sMP[256+tid] + sMP[384+tid]);
    __syncthreads();

    uint32_t qa[8][4];
    uint32_t ax[8][4];
    if (w < 13){
        // ---- Phase Q: gather(X) @ Ws + FC -> registers (A-frag layout) ----
        {
            uint32_t ag[8][4];
            const uint16_t* p1 = (r1 == 0) ? sPH : sK + sAct[r1-1]*136;
            const uint16_t* p2 = sK + sAct[r2-1]*136;
            #pragma unroll
            for (int kk = 0; kk < 8; kk++){
                ag[kk][0] = *(const uint32_t*)(p1 + kk*16 + qq*2);
                ag[kk][1] = *(const uint32_t*)(p2 + kk*16 + qq*2);
                ag[kk][2] = *(const uint32_t*)(p1 + kk*16 + qq*2 + 8);
                ag[kk][3] = *(const uint32_t*)(p2 + kk*16 + qq*2 + 8);
            }
            #pragma unroll 2
            for (int nt = 0; nt < 16; nt++){
                float acc[4] = {0.f,0.f,0.f,0.f};
                mma_chain(acc, ag, g_FWs, nt, lane);
                int d0 = nt*8 + qq*2;
                float2 fc = *(const float2*)(sFC + d0);
                int h = nt >> 1, odd = nt & 1;
                qa[h][odd*2]   = pk2(fc.x + acc[0], fc.y + acc[1]);  // row r1
                qa[h][odd*2+1] = pk2(fc.x + acc[2], fc.y + acc[3]);  // row r2
            }
        }
        // ---- own-row X fragments, then L2 phase ----
        {
            const uint16_t* p1 = sK + r1*136;
            const uint16_t* p2 = sK + r2*136;
            #pragma unroll
            for (int kk = 0; kk < 8; kk++){
                ax[kk][0] = *(const uint32_t*)(p1 + kk*16 + qq*2);
                ax[kk][1] = *(const uint32_t*)(p2 + kk*16 + qq*2);
                ax[kk][2] = *(const uint32_t*)(p1 + kk*16 + qq*2 + 8);
                ax[kk][3] = *(const uint32_t*)(p2 + kk*16 + qq*2 + 8);
            }
            #pragma unroll 2
            for (int nt = 0; nt < 16; nt++){
                float acc[4] = {0.f,0.f,0.f,0.f};
                mma_chain(acc, ax, g_FWc, nt, lane);
                int d0 = nt*8 + qq*2;
                *(uint32_t*)(sL + r1*136 + d0) = pk2(acc[0], acc[1]);
                *(uint32_t*)(sL + r2*136 + d0) = pk2(acc[2], acc[3]);
            }
        }
    }
    __syncthreads();   // all X reads complete before in-place K overwrite

    if (w < 13){
        // ---- Phase K (overwrite X rows r1,r2) + V (fp16) ----
        #pragma unroll 2
        for (int nt = 0; nt < 16; nt++){
            float acc[4] = {0.f,0.f,0.f,0.f};
            mma_chain(acc, ax, g_FWn, nt, lane);
            int d0 = nt*8 + qq*2;
            *(uint32_t*)(sK + r1*136 + d0) = pk2(acc[0], acc[1]);
            *(uint32_t*)(sK + r2*136 + d0) = pk2(acc[2], acc[3]);
        }
        #pragma unroll 2
        for (int nt = 16; nt < 32; nt++){
            float acc[4] = {0.f,0.f,0.f,0.f};
            mma_chain(acc, ax, g_FWn, nt, lane);
            int d0 = (nt - 16)*8 + qq*2;
            *(uint32_t*)(sV + r1*136 + d0) = f2h2(acc[0], acc[1]);
            *(uint32_t*)(sV + r2*136 + d0) = f2h2(acc[2], acc[3]);
        }
    }
    __syncthreads();

    float lp_acc = 0.f;
    if (w < 13){
        // ---- masks as split uint32 (bit = nt*2 + e) ----
        int act1 = sAct[r1], act2 = sAct[r2];
        uint32_t d1lo=0,d1hi=0,d2lo=0,d2hi=0,s1lo=0,s1hi=0,s2lo=0,s2hi=0;
        #pragma unroll
        for (int nt = 0; nt < 26; nt++){
            #pragma unroll
            for (int e = 0; e < 2; e++){
                int c = nt*8 + qq*2 + e;
                int p = (int)sPos[c];
                int bit = nt*2 + e;
                uint32_t bm = 1u << (bit & 31);
                if (bit < 32){
                    if (p < r1)    d1lo |= bm;
                    if (p < r2)    d2lo |= bm;
                    if (c == act1) s1lo |= bm;
                    if (c == act2) s2lo |= bm;
                } else {
                    if (p < r1)    d1hi |= bm;
                    if (p < r2)    d2hi |= bm;
                    if (c == act1) s1hi |= bm;
                    if (c == act2) s2hi |= bm;
                }
            }
        }

        // ---- ldmatrix lane addresses ----
        uint32_t sKu = (uint32_t)__cvta_generic_to_shared(sK);
        uint32_t sVu = (uint32_t)__cvta_generic_to_shared(sV);
        uint32_t sLu = (uint32_t)__cvta_generic_to_shared(sL);
        uint32_t kaddr = sKu + ((((lane & 7) + ((lane >> 4) << 3))*136
                                 + ((lane >> 3) & 1)*8) << 1);
        uint32_t vaddr = sVu + (((lane & 15)*136) << 1);
        uint32_t laddr = sLu + (((lane & 7)*136 + ((lane >> 3) & 1)*8) << 1);

        // ---- attention: all 8 heads, fully unrolled kt ----
        uint32_t la[8][4];
        #pragma unroll 1
        for (int h = 0; h < 8; h++){
            uint32_t sum1h = 0, sum2h = 0;
            float h0[4] = {0,0,0,0}, h1[4] = {0,0,0,0};
            uint32_t ka = kaddr + h*32;
            uint32_t va = vaddr + h*32;
            #pragma unroll
            for (int kt = 0; kt < 13; kt++){
                uint32_t kb0, kb1, kb2, kb3;
                ldmat_x4(kb0, kb1, kb2, kb3, ka + kt*4352);
                float s0[4] = {0,0,0,0}, s1[4] = {0,0,0,0};
                { uint32_t bb[2] = {kb0, kb1}; mma16816(s0, qa[h], bb); }
                { uint32_t bb[2] = {kb2, kb3}; mma16816(s1, qa[h], bb); }
                const int sh = kt*4;
                uint32_t m1 = (kt < 8) ? (d1lo >> sh) : (d1hi >> (sh - 32));
                uint32_t m2 = (kt < 8) ? (d2lo >> sh) : (d2hi >> (sh - 32));
                s0[0] = (m1 & 1) ? -100.f : s0[0];
                s0[1] = (m1 & 2) ? -100.f : s0[1];
                s1[0] = (m1 & 4) ? -100.f : s1[0];
                s1[1] = (m1 & 8) ? -100.f : s1[1];
                s0[2] = (m2 & 1) ? -100.f : s0[2];
                s0[3] = (m2 & 2) ? -100.f : s0[3];
                s1[2] = (m2 & 4) ? -100.f : s1[2];
                s1[3] = (m2 & 8) ? -100.f : s1[3];
                uint32_t pa[4];
                pa[0] = hex2(f2h2(s0[0], s0[1]));   // row r1, k 0-1
                pa[1] = hex2(f2h2(s0[2], s0[3]));   // row r2, k 0-1
                pa[2] = hex2(f2h2(s1[0], s1[1]));   // row r1, k 8-9
                pa[3] = hex2(f2h2(s1[2], s1[3]));   // row r2, k 8-9
                sum1h = hadd2u(sum1h, hadd2u(pa[0], pa[2]));
                sum2h = hadd2u(sum2h, hadd2u(pa[1], pa[3]));
                uint32_t v0, v1;
                ldmat_x2_trans(v0, v1, va + kt*4352);
                { uint32_t bv[2] = {v0, v1}; mma16816h(h0, pa, bv); }
                ldmat_x2_trans(v0, v1, va + kt*4352 + 16);
                { uint32_t bv[2] = {v0, v1}; mma16816h(h1, pa, bv); }
            }
            float2 a1 = h2f2(sum1h), a2 = h2f2(sum2h);
            float sum1 = qredsum(a1.x + a1.y);
            float sum2 = qredsum(a2.x + a2.y);
            float inv1 = 1.0f / sum1;
            float inv2 = (sum2 > 0.f) ? 1.0f / sum2 : 0.f;
            la[h][0] = pk2(h0[0]*inv1, h0[1]*inv1);
            la[h][1] = pk2(h0[2]*inv2, h0[3]*inv2);
            la[h][2] = pk2(h1[0]*inv1, h1[1]*inv1);
            la[h][3] = pk2(h1[2]*inv2, h1[3]*inv2);
        }

        // ---- logits: glimpse . L2^T via ldmatrix.x2 B-frags ----
        const float C1 = 2.0f*INV_SQRT_D*LOG2E;
        const float CE = -20.0f*LOG2E;
        float es1 = 0.f, es2 = 0.f, sv1 = 0.f, sv2 = 0.f;
        #pragma unroll 2
        for (int nt = 0; nt < 26; nt++){
            float acc[4] = {0,0,0,0};
            uint32_t la0 = laddr + nt*2176;
            #pragma unroll
            for (int h = 0; h < 8; h++){
                uint32_t b0, b1;
                ldmat_x2(b0, b1, la0 + h*32);
                uint32_t bb[2] = {b0, b1};
                mma16816(acc, la[h], bb);
            }
            const int sh = nt*2;
            uint32_t m1 = (nt < 16) ? (d1lo >> sh) : (d1hi >> (sh - 32));
            uint32_t m2 = (nt < 16) ? (d2lo >> sh) : (d2hi >> (sh - 32));
            uint32_t x1 = (nt < 16) ? (s1lo >> sh) : (s1hi >> (sh - 32));
            uint32_t x2 = (nt < 16) ? (s2lo >> sh) : (s2hi >> (sh - 32));
            #pragma unroll
            for (int e = 0; e < 2; e++){
                float u1 = fex2(C1*acc[e]);
                float r1f = frcpa(u1 + 1.f);
                float t1 = fmaf(-20.f, r1f, 10.f);
                float u2 = fex2(C1*acc[2+e]);
                float r2f = frcpa(u2 + 1.f);
                float t2 = fmaf(-20.f, r2f, 10.f);
                es1 += ((m1 >> e) & 1) ? 0.f : fex2(CE*r1f);
                es2 += ((m2 >> e) & 1) ? 0.f : fex2(CE*r2f);
                if ((x1 >> e) & 1) sv1 = t1;
                if ((x2 >> e) & 1) sv2 = t2;
            }
        }
        es1 = qredsum(es1); es2 = qredsum(es2);
        sv1 = qredsum(sv1); sv2 = qredsum(sv2);
        if (qq == 0){
            lp_acc += sv1 - 10.f - 0.6931471805599453f*flg2(es1);
            if (r2 < AA) lp_acc += sv2 - 10.f - 0.6931471805599453f*flg2(es2);
        }
    }

    lp_acc = wredsum(lp_acc);
    if (lane == 0) sLP[w] = lp_acc;
    __syncthreads();
    float* lp_out = mode ? (out + BB*AA) : out;
    if (tid == 0){
        float s = 0.f;
        #pragma unroll
        for (int k = 0; k < 16; k++) s += sLP[k];
        lp_out[b] = s;
    }
    if (mode){
        for (int i = tid; i < AA; i += 512) out[b*AA + i] = (float)sAct[i];
    }
}

// ---------------- launch -------------------------------------------------------
extern "C" void kernel_launch(void* const* d_in, const int* in_sizes, int n_in,
                              void* d_out, int out_size){
    const float* agent = (const float*)d_in[0];
    const int*   act   = (const int*)d_in[1];
    const float* Wp    = (const float*)d_in[2];
    const float* Wn    = (const float*)d_in[3];
    const float* Wf    = (const float*)d_in[4];
    const float* Ws    = (const float*)d_in[5];
    const float* Wo    = (const float*)d_in[6];
    float* out = (float*)d_out;

    cudaFuncSetAttribute(k_fused, cudaFuncAttributeMaxDynamicSharedMemorySize, FUSED_SMEM);

    k_prep<<<64, 256>>>(Ws, Wn, Wo);

    int mode = (out_size >= BB*AA) ? 1 : 0;
    k_fused<<<BB, 512, FUSED_SMEM>>>(agent, act, Wp, Wf, out, mode);
}

// round 14
// speedup vs baseline: 1.9500x; 1.0236x over previous
#include <cuda_runtime.h>
#include <cuda_bf16.h>
#include <cuda_fp16.h>
#include <cstdint>

#define BB 1024
#define AA 200
#define DD 128
#define INV_SQRT_D 0.08838834764831845f
#define LOG2E 1.4426950408889634f

// ---------------- persistent scratch: packed weight fragments only -------------
__device__ uint2 g_FWs[16*8*32];     // W_step fragments (pre-scaled by 0.25*log2e)
__device__ uint2 g_FWn[32*8*32];     // W_node cols 0..255 (K,V) fragments
__device__ uint2 g_FWc[16*8*32];     // Wc = Wn[:,256:384] @ Wo^T fragments

// ---------------- helpers ------------------------------------------------------
__device__ __forceinline__ uint16_t f2b(float x){
    return __bfloat16_as_ushort(__float2bfloat16(x));
}
__device__ __forceinline__ uint32_t pk2(float a, float b){
    return (uint32_t)f2b(a) | ((uint32_t)f2b(b) << 16);
}
__device__ __forceinline__ uint32_t f2h2(float lo, float hi){
    uint32_t r;
    asm("cvt.rn.f16x2.f32 %0, %1, %2;" : "=r"(r) : "f"(hi), "f"(lo));
    return r;
}
__device__ __forceinline__ uint32_t hex2(uint32_t x){
    uint32_t r;
    asm("ex2.approx.f16x2 %0, %1;" : "=r"(r) : "r"(x));
    return r;
}
__device__ __forceinline__ uint32_t hadd2u(uint32_t a, uint32_t b){
    __half2 x = *reinterpret_cast<__half2*>(&a);
    __half2 y = *reinterpret_cast<__half2*>(&b);
    __half2 r = __hadd2(x, y);
    return *reinterpret_cast<uint32_t*>(&r);
}
__device__ __forceinline__ float2 h2f2(uint32_t u){
    __half2 h = *reinterpret_cast<__half2*>(&u);
    return __half22float2(h);
}
__device__ __forceinline__ float fex2(float x){
    float r; asm("ex2.approx.ftz.f32 %0, %1;" : "=f"(r) : "f"(x)); return r;
}
__device__ __forceinline__ float frcpa(float x){
    float r; asm("rcp.approx.ftz.f32 %0, %1;" : "=f"(r) : "f"(x)); return r;
}
__device__ __forceinline__ float flg2(float x){
    float r; asm("lg2.approx.ftz.f32 %0, %1;" : "=f"(r) : "f"(x)); return r;
}
__device__ __forceinline__ float wredsum(float v){
    #pragma unroll
    for (int o = 16; o; o >>= 1) v += __shfl_xor_sync(0xffffffffu, v, o);
    return v;
}
__device__ __forceinline__ float qredsum(float v){
    v += __shfl_xor_sync(0xffffffffu, v, 1);
    v += __shfl_xor_sync(0xffffffffu, v, 2);
    return v;
}
__device__ __forceinline__ void mma16816(float* d, const uint32_t* a, const uint32_t* b){
    asm volatile(
      "mma.sync.aligned.m16n8k16.row.col.f32.bf16.bf16.f32 "
      "{%0,%1,%2,%3}, {%4,%5,%6,%7}, {%8,%9}, {%0,%1,%2,%3};\n"
      : "+f"(d[0]), "+f"(d[1]), "+f"(d[2]), "+f"(d[3])
      : "r"(a[0]), "r"(a[1]), "r"(a[2]), "r"(a[3]), "r"(b[0]), "r"(b[1]));
}
__device__ __forceinline__ void mma16816h(float* d, const uint32_t* a, const uint32_t* b){
    asm volatile(
      "mma.sync.aligned.m16n8k16.row.col.f32.f16.f16.f32 "
      "{%0,%1,%2,%3}, {%4,%5,%6,%7}, {%8,%9}, {%0,%1,%2,%3};\n"
      : "+f"(d[0]), "+f"(d[1]), "+f"(d[2]), "+f"(d[3])
      : "r"(a[0]), "r"(a[1]), "r"(a[2]), "r"(a[3]), "r"(b[0]), "r"(b[1]));
}
__device__ __forceinline__ void ldmat_x4(uint32_t& r0, uint32_t& r1, uint32_t& r2,
                                         uint32_t& r3, uint32_t addr){
    asm volatile("ldmatrix.sync.aligned.m8n8.x4.shared.b16 {%0,%1,%2,%3}, [%4];"
        : "=r"(r0), "=r"(r1), "=r"(r2), "=r"(r3) : "r"(addr));
}
__device__ __forceinline__ void ldmat_x2(uint32_t& r0, uint32_t& r1, uint32_t addr){
    asm volatile("ldmatrix.sync.aligned.m8n8.x2.shared.b16 {%0,%1}, [%2];"
        : "=r"(r0), "=r"(r1) : "r"(addr));
}
__device__ __forceinline__ void ldmat_x2_trans(uint32_t& r0, uint32_t& r1, uint32_t addr){
    asm volatile("ldmatrix.sync.aligned.m8n8.x2.trans.shared.b16 {%0,%1}, [%2];"
        : "=r"(r0), "=r"(r1) : "r"(addr));
}
// B-fragment chain from STAGED smem buffer
__device__ __forceinline__ void mma_chain_s(float* acc, const uint32_t a[8][4],
                                            const char* sWB, int nt, int lane){
    const uint2* F = (const uint2*)sWB;
    #pragma unroll
    for (int kk = 0; kk < 8; kk++){
        uint2 u = F[(nt*8 + kk)*32 + lane];
        uint32_t bb[2] = {u.x, u.y};
        mma16816(acc, a[kk], bb);
    }
}

// ---------------- prep: pack all B-fragments (Wc dot computed inline) ----------
__global__ void k_prep(const float* __restrict__ Ws, const float* __restrict__ Wn,
                       const float* __restrict__ Wo){
    int t = blockIdx.x*256 + threadIdx.x;
    int which, id;
    if (t < 4096)       { which = 0; id = t; }
    else if (t < 12288) { which = 1; id = t - 4096; }
    else                { which = 2; id = t - 12288; }
    int lane = id & 31, kk = (id >> 5) & 7, nt = id >> 8;
    int qq = lane & 3, gg = lane >> 2;
    int k0 = kk*16 + qq*2, n = nt*8 + gg;
    float v0, v1, v2, v3;
    if (which == 0){
        float s = 0.25f * LOG2E;
        v0 = Ws[(k0  )*128 + n]*s; v1 = Ws[(k0+1)*128 + n]*s;
        v2 = Ws[(k0+8)*128 + n]*s; v3 = Ws[(k0+9)*128 + n]*s;
    } else if (which == 1){
        v0 = Wn[(k0  )*384 + n]; v1 = Wn[(k0+1)*384 + n];
        v2 = Wn[(k0+8)*384 + n]; v3 = Wn[(k0+9)*384 + n];
    } else {
        const float* wo = Wo + n*128;
        const float* wa = Wn + (k0  )*384 + 256;
        const float* wb = Wn + (k0+1)*384 + 256;
        const float* wc = Wn + (k0+8)*384 + 256;
        const float* wd = Wn + (k0+9)*384 + 256;
        v0 = v1 = v2 = v3 = 0.f;
        #pragma unroll 4
        for (int d = 0; d < 128; d++){
            float o = wo[d];
            v0 = fmaf(wa[d], o, v0); v1 = fmaf(wb[d], o, v1);
            v2 = fmaf(wc[d], o, v2); v3 = fmaf(wd[d], o, v3);
        }
    }
    uint2 u; u.x = pk2(v0, v1); u.y = pk2(v2, v3);
    if (which == 0)      g_FWs[id] = u;
    else if (which == 1) g_FWn[id] = u;
    else                 g_FWc[id] = u;
}

// ---------------- fused kernel (512 threads; 13 working warps) -----------------
#define F_K   0
#define F_L   56576
#define F_V   113152
#define F_MP  169728
#define F_FC  171776
#define F_PH  172288
#define F_POS 172800
#define F_ACT 173312
#define F_LP  174208
#define F_WB  174272            // 32KB staging buffer, later reused as sLA (52KB)
#define FUSED_SMEM 227520

__global__ void __launch_bounds__(512) k_fused(
    const float* __restrict__ agent, const int* __restrict__ act_g,
    const float* __restrict__ Wp, const float* __restrict__ Wf,
    float* __restrict__ out, int mode)
{
    extern __shared__ char sm[];
    uint16_t* sK  = (uint16_t*)(sm + F_K);     // X -> K in place
    uint16_t* sL  = (uint16_t*)(sm + F_L);     // L2 (bf16)
    uint16_t* sV  = (uint16_t*)(sm + F_V);     // V (fp16)
    float*    sMP = (float*)(sm + F_MP);
    float*    sFC = (float*)(sm + F_FC);
    uint16_t* sPH = (uint16_t*)(sm + F_PH);
    int16_t*  sPos= (int16_t*)(sm + F_POS);
    int*      sAct= (int*)(sm + F_ACT);
    float*    sLP = (float*)(sm + F_LP);
    char*     sWB = sm + F_WB;

    int b = blockIdx.x, tid = threadIdx.x;
    int lane = tid & 31, w = tid >> 5, qq = lane & 3, gg = lane >> 2;
    int r1 = w*16 + gg, r2 = r1 + 8;

    // ---- stage FWs while loading X ----
    {
        const uint4* s = (const uint4*)g_FWs;
        uint4* d = (uint4*)sWB;
        #pragma unroll
        for (int i = 0; i < 4; i++) d[tid + 512*i] = s[tid + 512*i];
    }
    // ---- load X (fp32 -> bf16) + tables ----
    {
        const float2* Xg = (const float2*)(agent + (size_t)b*AA*DD);
        uint32_t* dX = (uint32_t*)sK;
        for (int i = tid; i < AA*64; i += 512){
            int r = i >> 6, c = i & 63;
            float2 v = Xg[i];
            dX[r*68 + c] = pk2(v.x, v.y);
        }
        for (int i = 200*68 + tid; i < 208*68; i += 512) dX[i] = 0;
        if (tid < 128) sPH[tid] = f2b(Wp[tid]);
        if (tid < 256) sPos[tid] = -1;
        if (tid < 208) sAct[tid] = (tid < AA) ? act_g[b*AA + tid] : 0;
    }
    __syncthreads();
    if (tid < AA) sPos[sAct[tid]] = (int16_t)tid;
    // ---- FC stage A: column sums from bf16 X in smem ----
    {
        int part = tid >> 7, j = tid & 127;
        const uint16_t* xp = sK + part*50*136 + j;
        float s = 0.f;
        #pragma unroll 5
        for (int r = 0; r < 50; r++)
            s += __uint_as_float(((uint32_t)xp[r*136]) << 16);
        sMP[tid] = s;
    }
    __syncthreads();
    if (tid < 128)
        sFC[tid] = (sMP[tid] + sMP[128+tid] + sMP[256+tid] + sMP[384+tid]) * (1.0f/AA);
    __syncthreads();
    {
        int q4 = tid >> 7, j = tid & 127;
        float accB = 0.f;
        #pragma unroll 8
        for (int d = q4*32; d < q4*32 + 32; d++) accB = fmaf(sFC[d], Wf[d*128 + j], accB);
        __syncthreads();
        sMP[tid] = accB;
    }
    __syncthreads();
    if (tid < 128)
        sFC[tid] = (0.25f*LOG2E)*(sMP[tid] + sMP[128+tid] + sMP[256+tid] + sMP[384+tid]);
    __syncthreads();

    uint32_t qa[8][4];
    uint32_t ax[8][4];
    // ---- Phase Q: gather(X) @ Ws + FC -> qa registers (A-frag layout) ----
    if (w < 13){
        uint32_t ag[8][4];
        const uint16_t* p1 = (r1 == 0) ? sPH : sK + sAct[r1-1]*136;
        const uint16_t* p2 = sK + sAct[r2-1]*136;
        #pragma unroll
        for (int kk = 0; kk < 8; kk++){
            ag[kk][0] = *(const uint32_t*)(p1 + kk*16 + qq*2);
            ag[kk][1] = *(const uint32_t*)(p2 + kk*16 + qq*2);
            ag[kk][2] = *(const uint32_t*)(p1 + kk*16 + qq*2 + 8);
            ag[kk][3] = *(const uint32_t*)(p2 + kk*16 + qq*2 + 8);
        }
        #pragma unroll
        for (int nt = 0; nt < 16; nt++){            // FULL unroll: qa stays in regs
            float acc[4] = {0.f,0.f,0.f,0.f};
            mma_chain_s(acc, ag, sWB, nt, lane);
            int d0 = nt*8 + qq*2;
            float2 fc = *(const float2*)(sFC + d0);
            const int h = nt >> 1, odd = nt & 1;
            qa[h][odd*2]   = pk2(fc.x + acc[0], fc.y + acc[1]);  // row r1
            qa[h][odd*2+1] = pk2(fc.x + acc[2], fc.y + acc[3]);  // row r2
        }
    }
    __syncthreads();      // Q done with FWs
    {
        const uint4* s = (const uint4*)g_FWc;
        uint4* d = (uint4*)sWB;
        #pragma unroll
        for (int i = 0; i < 4; i++) d[tid + 512*i] = s[tid + 512*i];
    }
    __syncthreads();      // FWc staged
    if (w < 13){
        // ---- own-row X fragments, then L2 phase ----
        const uint16_t* p1 = sK + r1*136;
        const uint16_t* p2 = sK + r2*136;
        #pragma unroll
        for (int kk = 0; kk < 8; kk++){
            ax[kk][0] = *(const uint32_t*)(p1 + kk*16 + qq*2);
            ax[kk][1] = *(const uint32_t*)(p2 + kk*16 + qq*2);
            ax[kk][2] = *(const uint32_t*)(p1 + kk*16 + qq*2 + 8);
            ax[kk][3] = *(const uint32_t*)(p2 + kk*16 + qq*2 + 8);
        }
        #pragma unroll 2
        for (int nt = 0; nt < 16; nt++){
            float acc[4] = {0.f,0.f,0.f,0.f};
            mma_chain_s(acc, ax, sWB, nt, lane);
            int d0 = nt*8 + qq*2;
            *(uint32_t*)(sL + r1*136 + d0) = pk2(acc[0], acc[1]);
            *(uint32_t*)(sL + r2*136 + d0) = pk2(acc[2], acc[3]);
        }
    }
    __syncthreads();      // all X reads complete + L2 done with sWB
    {
        const uint4* s = (const uint4*)g_FWn;
        uint4* d = (uint4*)sWB;
        #pragma unroll
        for (int i = 0; i < 4; i++) d[tid + 512*i] = s[tid + 512*i];
    }
    __syncthreads();      // FWn K-half staged
    if (w < 13){
        // ---- Phase K (overwrite X rows r1,r2) ----
        #pragma unroll 2
        for (int nt = 0; nt < 16; nt++){
            float acc[4] = {0.f,0.f,0.f,0.f};
            mma_chain_s(acc, ax, sWB, nt, lane);
            int d0 = nt*8 + qq*2;
            *(uint32_t*)(sK + r1*136 + d0) = pk2(acc[0], acc[1]);
            *(uint32_t*)(sK + r2*136 + d0) = pk2(acc[2], acc[3]);
        }
    }
    __syncthreads();      // K done with sWB
    {
        const uint4* s = (const uint4*)(g_FWn + 4096);
        uint4* d = (uint4*)sWB;
        #pragma unroll
        for (int i = 0; i < 4; i++) d[tid + 512*i] = s[tid + 512*i];
    }
    __syncthreads();      // FWn V-half staged
    if (w < 13){
        // ---- Phase V (fp16) ----
        #pragma unroll 2
        for (int nt = 0; nt < 16; nt++){
            float acc[4] = {0.f,0.f,0.f,0.f};
            mma_chain_s(acc, ax, sWB, nt, lane);
            int d0 = nt*8 + qq*2;
            *(uint32_t*)(sV + r1*136 + d0) = f2h2(acc[0], acc[1]);
            *(uint32_t*)(sV + r2*136 + d0) = f2h2(acc[2], acc[3]);
        }
    }
    __syncthreads();      // everything ready for decode; sWB becomes sLA

    uint4* sLAv = (uint4*)sWB;
    float lp_acc = 0.f;
    if (w < 13){
        // ---- masks as split uint32 (bit = nt*2 + e) ----
        int act1 = sAct[r1], act2 = sAct[r2];
        uint32_t d1lo=0,d1hi=0,d2lo=0,d2hi=0,s1lo=0,s1hi=0,s2lo=0,s2hi=0;
        #pragma unroll
        for (int nt = 0; nt < 26; nt++){
            #pragma unroll
            for (int e = 0; e < 2; e++){
                int c = nt*8 + qq*2 + e;
                int p = (int)sPos[c];
                int bit = nt*2 + e;
                uint32_t bm = 1u << (bit & 31);
                if (bit < 32){
                    if (p < r1)    d1lo |= bm;
                    if (p < r2)    d2lo |= bm;
                    if (c == act1) s1lo |= bm;
                    if (c == act2) s2lo |= bm;
                } else {
                    if (p < r1)    d1hi |= bm;
                    if (p < r2)    d2hi |= bm;
                    if (c == act1) s1hi |= bm;
                    if (c == act2) s2hi |= bm;
                }
            }
        }

        // ---- ldmatrix lane addresses ----
        uint32_t sKu = (uint32_t)__cvta_generic_to_shared(sK);
        uint32_t sVu = (uint32_t)__cvta_generic_to_shared(sV);
        uint32_t sLu = (uint32_t)__cvta_generic_to_shared(sL);
        uint32_t kaddr = sKu + ((((lane & 7) + ((lane >> 4) << 3))*136
                                 + ((lane >> 3) & 1)*8) << 1);
        uint32_t vaddr = sVu + (((lane & 15)*136) << 1);
        uint32_t laddr = sLu + (((lane & 7)*136 + ((lane >> 3) & 1)*8) << 1);

        // ---- attention: 4 head-pairs, fully static, 2 heads interleaved ----
        #pragma unroll
        for (int hp = 0; hp < 4; hp++){
            const int hA = hp*2, hB = hA + 1;
            uint32_t sum1A = 0, sum2A = 0, sum1B = 0, sum2B = 0;
            float h0A[4] = {0,0,0,0}, h1A[4] = {0,0,0,0};
            float h0B[4] = {0,0,0,0}, h1B[4] = {0,0,0,0};
            #pragma unroll
            for (int kt = 0; kt < 13; kt++){
                const int sh = kt*4;
                uint32_t m1 = (kt < 8) ? (d1lo >> sh) : (d1hi >> (sh - 32));
                uint32_t m2 = (kt < 8) ? (d2lo >> sh) : (d2hi >> (sh - 32));
                uint32_t ka0,ka1,ka2,ka3, kb0,kb1,kb2,kb3;
                ldmat_x4(ka0, ka1, ka2, ka3, kaddr + hA*32 + kt*4352);
                ldmat_x4(kb0, kb1, kb2, kb3, kaddr + hB*32 + kt*4352);
                float sA0[4]={0,0,0,0}, sA1[4]={0,0,0,0};
                float sB0[4]={0,0,0,0}, sB1[4]={0,0,0,0};
                { uint32_t bb[2]={ka0,ka1}; mma16816(sA0, qa[hA], bb); }
                { uint32_t bb[2]={ka2,ka3}; mma16816(sA1, qa[hA], bb); }
                { uint32_t bb[2]={kb0,kb1}; mma16816(sB0, qa[hB], bb); }
                { uint32_t bb[2]={kb2,kb3}; mma16816(sB1, qa[hB], bb); }
                sA0[0] = (m1 & 1) ? -100.f : sA0[0];
                sA0[1] = (m1 & 2) ? -100.f : sA0[1];
                sA1[0] = (m1 & 4) ? -100.f : sA1[0];
                sA1[1] = (m1 & 8) ? -100.f : sA1[1];
                sA0[2] = (m2 & 1) ? -100.f : sA0[2];
                sA0[3] = (m2 & 2) ? -100.f : sA0[3];
                sA1[2] = (m2 & 4) ? -100.f : sA1[2];
                sA1[3] = (m2 & 8) ? -100.f : sA1[3];
                sB0[0] = (m1 & 1) ? -100.f : sB0[0];
                sB0[1] = (m1 & 2) ? -100.f : sB0[1];
                sB1[0] = (m1 & 4) ? -100.f : sB1[0];
                sB1[1] = (m1 & 8) ? -100.f : sB1[1];
                sB0[2] = (m2 & 1) ? -100.f : sB0[2];
                sB0[3] = (m2 & 2) ? -100.f : sB0[3];
                sB1[2] = (m2 & 4) ? -100.f : sB1[2];
                sB1[3] = (m2 & 8) ? -100.f : sB1[3];
                uint32_t pA[4], pB[4];
                pA[0] = hex2(f2h2(sA0[0], sA0[1]));
                pA[1] = hex2(f2h2(sA0[2], sA0[3]));
                pA[2] = hex2(f2h2(sA1[0], sA1[1]));
                pA[3] = hex2(f2h2(sA1[2], sA1[3]));
                pB[0] = hex2(f2h2(sB0[0], sB0[1]));
                pB[1] = hex2(f2h2(sB0[2], sB0[3]));
                pB[2] = hex2(f2h2(sB1[0], sB1[1]));
                pB[3] = hex2(f2h2(sB1[2], sB1[3]));
                sum1A = hadd2u(sum1A, hadd2u(pA[0], pA[2]));
                sum2A = hadd2u(sum2A, hadd2u(pA[1], pA[3]));
                sum1B = hadd2u(sum1B, hadd2u(pB[0], pB[2]));
                sum2B = hadd2u(sum2B, hadd2u(pB[1], pB[3]));
                uint32_t v0, v1;
                ldmat_x2_trans(v0, v1, vaddr + hA*32 + kt*4352);
                { uint32_t bv[2]={v0,v1}; mma16816h(h0A, pA, bv); }
                ldmat_x2_trans(v0, v1, vaddr + hA*32 + kt*4352 + 16);
                { uint32_t bv[2]={v0,v1}; mma16816h(h1A, pA, bv); }
                ldmat_x2_trans(v0, v1, vaddr + hB*32 + kt*4352);
                { uint32_t bv[2]={v0,v1}; mma16816h(h0B, pB, bv); }
                ldmat_x2_trans(v0, v1, vaddr + hB*32 + kt*4352 + 16);
                { uint32_t bv[2]={v0,v1}; mma16816h(h1B, pB, bv); }
            }
            {
                float2 a1 = h2f2(sum1A), a2 = h2f2(sum2A);
                float s1 = qredsum(a1.x + a1.y);
                float s2 = qredsum(a2.x + a2.y);
                float i1 = 1.0f / s1;
                float i2 = (s2 > 0.f) ? 1.0f / s2 : 0.f;
                uint4 LA;
                LA.x = pk2(h0A[0]*i1, h0A[1]*i1);
                LA.y = pk2(h0A[2]*i2, h0A[3]*i2);
                LA.z = pk2(h1A[0]*i1, h1A[1]*i1);
                LA.w = pk2(h1A[2]*i2, h1A[3]*i2);
                sLAv[(w*8 + hA)*32 + lane] = LA;
            }
            {
                float2 a1 = h2f2(sum1B), a2 = h2f2(sum2B);
                float s1 = qredsum(a1.x + a1.y);
                float s2 = qredsum(a2.x + a2.y);
                float i1 = 1.0f / s1;
                float i2 = (s2 > 0.f) ? 1.0f / s2 : 0.f;
                uint4 LB;
                LB.x = pk2(h0B[0]*i1, h0B[1]*i1);
                LB.y = pk2(h0B[2]*i2, h0B[3]*i2);
                LB.z = pk2(h1B[0]*i1, h1B[1]*i1);
                LB.w = pk2(h1B[2]*i2, h1B[3]*i2);
                sLAv[(w*8 + hB)*32 + lane] = LB;
            }
        }

        // ---- reload la fragments (own-warp, own-lane; no sync needed) ----
        uint32_t la[8][4];
        #pragma unroll
        for (int h = 0; h < 8; h++){
            uint4 u = sLAv[(w*8 + h)*32 + lane];
            la[h][0] = u.x; la[h][1] = u.y; la[h][2] = u.z; la[h][3] = u.w;
        }

        // ---- logits: glimpse . L2^T via ldmatrix.x2 B-frags ----
        const float C1 = 2.0f*INV_SQRT_D*LOG2E;
        const float CE = -20.0f*LOG2E;
        float es1 = 0.f, es2 = 0.f, sv1 = 0.f, sv2 = 0.f;
        #pragma unroll 2
        for (int nt = 0; nt < 26; nt++){
            float acc[4] = {0,0,0,0};
            uint32_t la0 = laddr + nt*2176;
            #pragma unroll
            for (int h = 0; h < 8; h++){
                uint32_t b0, b1;
                ldmat_x2(b0, b1, la0 + h*32);
                uint32_t bb[2] = {b0, b1};
                mma16816(acc, la[h], bb);
            }
            const int sh = nt*2;
            uint32_t m1 = (nt < 16) ? (d1lo >> sh) : (d1hi >> (sh - 32));
            uint32_t m2 = (nt < 16) ? (d2lo >> sh) : (d2hi >> (sh - 32));
            uint32_t x1 = (nt < 16) ? (s1lo >> sh) : (s1hi >> (sh - 32));
            uint32_t x2 = (nt < 16) ? (s2lo >> sh) : (s2hi >> (sh - 32));
            #pragma unroll
            for (int e = 0; e < 2; e++){
                float u1 = fex2(C1*acc[e]);
                float r1f = frcpa(u1 + 1.f);
                float t1 = fmaf(-20.f, r1f, 10.f);
                float u2 = fex2(C1*acc[2+e]);
                float r2f = frcpa(u2 + 1.f);
                float t2 = fmaf(-20.f, r2f, 10.f);
                es1 += ((m1 >> e) & 1) ? 0.f : fex2(CE*r1f);
                es2 += ((m2 >> e) & 1) ? 0.f : fex2(CE*r2f);
                if ((x1 >> e) & 1) sv1 = t1;
                if ((x2 >> e) & 1) sv2 = t2;
            }
        }
        es1 = qredsum(es1); es2 = qredsum(es2);
        sv1 = qredsum(sv1); sv2 = qredsum(sv2);
        if (qq == 0){
            lp_acc += sv1 - 10.f - 0.6931471805599453f*flg2(es1);
            if (r2 < AA) lp_acc += sv2 - 10.f - 0.6931471805599453f*flg2(es2);
        }
    }

    lp_acc = wredsum(lp_acc);
    if (lane == 0) sLP[w] = lp_acc;
    __syncthreads();
    float* lp_out = mode ? (out + BB*AA) : out;
    if (tid == 0){
        float s = 0.f;
        #pragma unroll
        for (int k = 0; k < 16; k++) s += sLP[k];
        lp_out[b] = s;
    }
    if (mode){
        for (int i = tid; i < AA; i += 512) out[b*AA + i] = (float)sAct[i];
    }
}

// ---------------- launch -------------------------------------------------------
extern "C" void kernel_launch(void* const* d_in, const int* in_sizes, int n_in,
                              void* d_out, int out_size){
    const float* agent = (const float*)d_in[0];
    const int*   act   = (const int*)d_in[1];
    const float* Wp    = (const float*)d_in[2];
    const float* Wn    = (const float*)d_in[3];
    const float* Wf    = (const float*)d_in[4];
    const float* Ws    = (const float*)d_in[5];
    const float* Wo    = (const float*)d_in[6];
    float* out = (float*)d_out;

    cudaFuncSetAttribute(k_fused, cudaFuncAttributeMaxDynamicSharedMemorySize, FUSED_SMEM);

    k_prep<<<64, 256>>>(Ws, Wn, Wo);

    int mode = (out_size >= BB*AA) ? 1 : 0;
    k_fused<<<BB, 512, FUSED_SMEM>>>(agent, act, Wp, Wf, out, mode);
}